// round 16
// baseline (speedup 1.0000x reference)
#include <cuda_runtime.h>

#define TI 128          /* i-extent per block */
#define TJ 32           /* j-extent per block */
#define NT 256
#define MAX_TILES 64
#define MAX_N (MAX_TILES * TI)
#define MAX_B (MAX_TILES * (MAX_TILES + 1) * 2)
#define NCELL 4
#define NCELL3 (NCELL * NCELL * NCELL)
#define FAR_RSQ 30.0f   /* erf==1, gauss==0 (fp32) beyond this */

__device__ double       g_part[MAX_B];
__device__ unsigned int g_count;     // zero at load; last block resets each launch
__device__ int          g_perm[MAX_N];

// SIGMA=1 -> a=1/sqrt(2), c=2a/sqrt(pi).  KEXP = -0.5*log2(e)
#define C_CONST   0.79788456080286536f
#define PA_CONST  0.23174530376899319f   /* 0.3275911 * a */
#define KEXP     -0.72134752044448170f

__device__ __forceinline__ float ex2f(float x)  { float r; asm("ex2.approx.f32 %0,%1;"   : "=f"(r) : "f"(x)); return r; }
__device__ __forceinline__ float rcpf(float x)  { float r; asm("rcp.approx.f32 %0,%1;"   : "=f"(r) : "f"(x)); return r; }
__device__ __forceinline__ float rsqf(float x)  { float r; asm("rsqrt.approx.f32 %0,%1;" : "=f"(r) : "f"(x)); return r; }

// ---------------- deterministic counting sort by spatial cell ----------------
// One block per cell. Stable (index-order) scatter -> g_perm is deterministic.
__device__ __forceinline__ int cell_of(const float* __restrict__ r, int k) {
    const float cs = (float)NCELL / 20.0f;
    int cx = (int)(r[3*k]   * cs);
    int cy = (int)(r[3*k+1] * cs);
    int cz = (int)(r[3*k+2] * cs);
    cx = min(max(cx, 0), NCELL - 1);
    cy = min(max(cy, 0), NCELL - 1);
    cz = min(max(cz, 0), NCELL - 1);
    return (cx * NCELL + cy) * NCELL + cz;
}

__global__ void __launch_bounds__(256) sort_kernel(const float* __restrict__ r, int n)
{
    const int c    = blockIdx.x;        // this block's cell
    const int tx   = threadIdx.x;
    const int lane = tx & 31;
    const int wid  = tx >> 5;

    __shared__ int s_less;
    __shared__ int s_wcnt[8];
    if (tx == 0) s_less = 0;
    __syncthreads();

    // pass 1: count particles in cells < c (start offset); integer atomics exact
    int cl = 0;
    for (int k = tx; k < n; k += 256)
        cl += (cell_of(r, k) < c) ? 1 : 0;
    atomicAdd(&s_less, cl);
    __syncthreads();
    int base = s_less;

    // pass 2: stable scatter of this cell's members, chunks of 256 in index order
    for (int k0 = 0; k0 < n; k0 += 256) {
        int k = k0 + tx;
        bool flag = (k < n) && (cell_of(r, k) == c);
        unsigned bal = __ballot_sync(0xffffffffu, flag);
        int within = __popc(bal & ((1u << lane) - 1u));
        if (lane == 0) s_wcnt[wid] = __popc(bal);
        __syncthreads();
        int wofs = 0, tot = 0;
        #pragma unroll
        for (int w = 0; w < 8; w++) {
            int v = s_wcnt[w];
            if (w < wid) wofs += v;
            tot += v;
        }
        if (flag) g_perm[base + wofs + within] = k;
        base += tot;
        __syncthreads();
    }
}

// ---------------- pair interaction ----------------
template<bool DIAG>
__device__ __forceinline__ float pair_full(
    float rsq, float rix_unused, float qi,
    float uix, float uiy, float uiz,
    float dx, float dy, float dz,
    const float4& rqj, const float4& ujv, bool self)
{
    float rinv  = rsqf(rsq);                 // MUFU.RSQ
    float rr    = rsq * rinv;                // |r|
    float gauss = ex2f(KEXP * rsq);          // exp(-(a r)^2)

    // Abramowitz-Stegun 7.1.26 (|err| < 1.5e-7); 'a' folded into PA_CONST
    float t = rcpf(fmaf(PA_CONST, rr, 1.0f));
    float poly = fmaf(t, fmaf(t, fmaf(t, fmaf(t, 1.061405429f, -1.453152027f),
                                      1.421413741f), -0.284496736f), 0.254829592f);
    float erfv = fmaf(-t * poly, gauss, 1.0f);

    float rinv2 = rinv * rinv;
    float e1 = erfv * rinv;                          // erf/r
    float e3 = e1 * rinv2;                           // erf/r^3
    float ncg = -C_CONST * gauss;                    // -c*gauss
    float s1 = fmaf(ncg, rinv2, e3);                 // e3 - c*gauss/r^2
    float s2 = fmaf(2.0f, s1, e3 + ncg);             // 3e3 - 2g2 - c*gauss

    float qj  = rqj.w;
    float udi = fmaf(uix, dx, fmaf(uiy, dy, uiz * dz));
    float udj = fmaf(ujv.x, dx, fmaf(ujv.y, dy, ujv.z * dz));
    float uu  = fmaf(uix, ujv.x, fmaf(uiy, ujv.y, uiz * ujv.z));

    float pr = (qi * qj) * e1;                         // qq
    pr = fmaf(-s1, fmaf(qj, udi, -(qi * udj)), pr);    // qu
    pr = fmaf(s1, uu, pr);                             // uu iso
    pr = fmaf(-s2, (udi * udj) * rinv2, pr);           // uu aniso

    if (DIAG) pr = self ? 0.0f : pr;
    return pr;
}

__device__ __forceinline__ float pair_far(
    float rsq, float qi,
    float uix, float uiy, float uiz,
    float dx, float dy, float dz,
    const float4& rqj, const float4& ujv)
{
    // rsq > 30: erf == 1, gauss == 0 (to fp32) -> point charge+dipole form
    float rinv  = rsqf(rsq);
    float rinv2 = rinv * rinv;
    float e3    = rinv * rinv2;

    float qj  = rqj.w;
    float udi = fmaf(uix, dx, fmaf(uiy, dy, uiz * dz));
    float udj = fmaf(ujv.x, dx, fmaf(ujv.y, dy, ujv.z * dz));
    float uu  = fmaf(uix, ujv.x, fmaf(uiy, ujv.y, uiz * ujv.z));

    float pr = (qi * qj) * rinv;                       // qq
    pr = fmaf(-e3, fmaf(qj, udi, -(qi * udj)), pr);    // qu  (s1 = e3)
    pr = fmaf(e3, uu, pr);                             // uu iso
    float nm3 = -3.0f * e3;                            // s2 = 3*e3
    pr = fmaf(nm3, (udi * udj) * rinv2, pr);           // uu aniso
    return pr;
}

__global__ void __launch_bounds__(NT, 4) pair_kernel(
    const float* __restrict__ q, const float* __restrict__ r,
    const float* __restrict__ u, int n, int tiles, float outscale,
    float* __restrict__ out)
{
    // ---- block -> (tile-pair, j-quarter) ----
    int p4 = blockIdx.x;
    int pr0 = p4 >> 2;
    const int js = p4 & 3;
    int bi = 0;
    while (pr0 >= tiles - bi) { pr0 -= tiles - bi; bi++; }
    const int bj = bi + pr0;
    const bool diag = (bi == bj);

    __shared__ float4 s_rq[TJ];   // (x, y, z, q) of sorted j
    __shared__ float4 s_u[TJ];    // (ux, uy, uz, 0)

    const int tx = threadIdx.x;
    const int il = tx & (TI - 1);     // sorted i-lane 0..127
    const int jg = tx >> 7;           // j-group 0..1 (16 j's each)
    const int i  = bi * TI + il;      // sorted index
    const int j0 = bj * TI + js * TJ; // sorted index base

    if (tx < TJ) {
        int j = j0 + tx;
        float4 v;
        if (j < n) {
            int jp = g_perm[j];
            v.x = r[3*jp]; v.y = r[3*jp+1]; v.z = r[3*jp+2]; v.w = q[jp];
        } else {
            v.x = 1.0e7f + (float)j; v.y = 0.f; v.z = 0.f; v.w = 0.f;
        }
        s_rq[tx] = v;
    } else if (tx < 2 * TJ) {
        int jt = tx - TJ, j = j0 + jt;
        float4 v;
        if (j < n) {
            int jp = g_perm[j];
            v.x = u[3*jp]; v.y = u[3*jp+1]; v.z = u[3*jp+2]; v.w = 0.f;
        } else {
            v = make_float4(0.f, 0.f, 0.f, 0.f);
        }
        s_u[jt] = v;
    }

    float qi = 0.f, rix, riy = 0.f, riz = 0.f, uix = 0.f, uiy = 0.f, uiz = 0.f;
    if (i < n) {
        int ip = g_perm[i];
        qi  = q[ip];
        rix = r[3*ip]; riy = r[3*ip+1]; riz = r[3*ip+2];
        uix = u[3*ip]; uiy = u[3*ip+1]; uiz = u[3*ip+2];
    } else {
        rix = 2.0e7f + (float)i;   // far, q=u=0 -> zero contribution
    }
    __syncthreads();

    double acc = 0.0;
    const int jbeg = jg * (TJ / 2);   // 16 j's per thread; j is warp-uniform

    #pragma unroll 1
    for (int g = 0; g < TJ / 2; g += 4) {
        float facc = 0.0f;
        #pragma unroll
        for (int k = 0; k < 4; k++) {
            const int jj = jbeg + g + k;
            float4 rqj = s_rq[jj];
            float4 ujv = s_u[jj];
            float dx = rqj.x - rix;
            float dy = rqj.y - riy;
            float dz = rqj.z - riz;
            float rsq = fmaf(dx, dx, fmaf(dy, dy, dz * dz));

            bool self = false;
            if (diag) {
                self = ((j0 + jj) == i);
                if (self) rsq = 1.0f;          // finite; masked in full path
            }

            // warp-uniform branch: j shared by all 32 lanes
            if (__any_sync(0xffffffffu, rsq < FAR_RSQ)) {
                if (diag)
                    facc += pair_full<true>(rsq, 0.f, qi, uix, uiy, uiz,
                                            dx, dy, dz, rqj, ujv, self);
                else
                    facc += pair_full<false>(rsq, 0.f, qi, uix, uiy, uiz,
                                             dx, dy, dz, rqj, ujv, false);
            } else {
                facc += pair_far(rsq, qi, uix, uiy, uiz, dx, dy, dz, rqj, ujv);
            }
        }
        acc += (double)facc;
    }

    if (diag) acc *= 0.5;   // diagonal tile double-counts each unordered pair

    // ---- deterministic block reduction ----
    #pragma unroll
    for (int off = 16; off > 0; off >>= 1)
        acc += __shfl_down_sync(0xffffffffu, acc, off);

    __shared__ double warp_s[NT / 32];
    if ((tx & 31) == 0) warp_s[tx >> 5] = acc;
    __syncthreads();

    __shared__ bool isLast;
    if (tx == 0) {
        double s = 0.0;
        #pragma unroll
        for (int w = 0; w < NT / 32; w++) s += warp_s[w];
        g_part[blockIdx.x] = s;
        __threadfence();
        unsigned c = atomicAdd(&g_count, 1u);
        isLast = (c == gridDim.x - 1);
    }
    __syncthreads();

    // ---- last block: final reduction (fixed order -> deterministic) ----
    if (isLast) {
        __threadfence();
        const int nB = gridDim.x;
        double s = 0.0;
        for (int k = tx; k < nB; k += NT) s += g_part[k];

        #pragma unroll
        for (int off = 16; off > 0; off >>= 1)
            s += __shfl_down_sync(0xffffffffu, s, off);

        __shared__ double fin_s[NT / 32];
        if ((tx & 31) == 0) fin_s[tx >> 5] = s;
        __syncthreads();
        if (tx == 0) {
            double tot = 0.0;
            #pragma unroll
            for (int w = 0; w < NT / 32; w++) tot += fin_s[w];
            out[0] = (float)(tot * (double)outscale);
            g_count = 0;   // reset for next graph replay
        }
    }
}

extern "C" void kernel_launch(void* const* d_in, const int* in_sizes, int n_in,
                              void* d_out, int out_size)
{
    const float* q = (const float*)d_in[0];
    const float* r = (const float*)d_in[1];
    const float* u = (const float*)d_in[2];
    float* out = (float*)d_out;

    int n = in_sizes[0];
    if (n > MAX_N) n = MAX_N;
    int tiles = (n + TI - 1) / TI;
    if (tiles > MAX_TILES) tiles = MAX_TILES;

    int nB = tiles * (tiles + 1) * 2;   // 4 j-quarter blocks per triangular tile-pair
    float outscale = (float)(90.0474 / 6.283185307179586476925286766559);

    sort_kernel<<<NCELL3, 256>>>(r, n);
    pair_kernel<<<nB, NT>>>(q, r, u, n, tiles, outscale, out);
}

// round 17
// speedup vs baseline: 1.2759x; 1.2759x over previous
#include <cuda_runtime.h>

#define TI 128          /* i-extent per block */
#define TJ 32           /* j-extent per block */
#define NT 256
#define MAX_TILES 64
#define MAX_B (MAX_TILES * (MAX_TILES + 1) * 2)

__device__ double       g_part[MAX_B];
__device__ unsigned int g_count;   // zero at load; last block resets each launch

// SIGMA=1 -> a=1/sqrt(2), c=2a/sqrt(pi).  KEXP = -0.5*log2(e)
#define C_CONST   0.79788456080286536f
#define PA_CONST  0.23174530376899319f   /* 0.3275911 * a */
#define KEXP     -0.72134752044448170f

__device__ __forceinline__ float ex2f(float x)  { float r; asm("ex2.approx.f32 %0,%1;"   : "=f"(r) : "f"(x)); return r; }
__device__ __forceinline__ float rcpf(float x)  { float r; asm("rcp.approx.f32 %0,%1;"   : "=f"(r) : "f"(x)); return r; }
__device__ __forceinline__ float rsqf(float x)  { float r; asm("rsqrt.approx.f32 %0,%1;" : "=f"(r) : "f"(x)); return r; }

template<bool DIAG>
__device__ __forceinline__ float pair_term(
    float rix, float riy, float riz, float qi,
    float uix, float uiy, float uiz,
    const float4& rqj, const float4& ujv,
    bool self)
{
    float dx = rqj.x - rix;
    float dy = rqj.y - riy;
    float dz = rqj.z - riz;
    float rsq = fmaf(dx, dx, fmaf(dy, dy, dz * dz));

    if (DIAG) { if (self) rsq = 1.0f; }      // keep math finite; masked below

    float rinv  = rsqf(rsq);                 // MUFU.RSQ
    float rr    = rsq * rinv;                // |r|
    float gauss = ex2f(KEXP * rsq);          // exp(-(a r)^2)

    // Abramowitz-Stegun 7.1.26 (|err| < 1.5e-7); 'a' folded into PA_CONST
    float t = rcpf(fmaf(PA_CONST, rr, 1.0f));
    float poly = fmaf(t, fmaf(t, fmaf(t, fmaf(t, 1.061405429f, -1.453152027f),
                                      1.421413741f), -0.284496736f), 0.254829592f);
    float erfv = fmaf(-t * poly, gauss, 1.0f);

    float rinv2 = rinv * rinv;
    float e1 = erfv * rinv;                          // erf/r
    float e3 = e1 * rinv2;                           // erf/r^3
    float ncg = -C_CONST * gauss;                    // -c*gauss
    float s1 = fmaf(ncg, rinv2, e3);                 // e3 - c*gauss/r^2
    float s2 = fmaf(2.0f, s1, e3 + ncg);             // 3e3 - 2g2 - c*gauss

    float qj  = rqj.w;
    float udi = fmaf(uix, dx, fmaf(uiy, dy, uiz * dz));
    float udj = fmaf(ujv.x, dx, fmaf(ujv.y, dy, ujv.z * dz));
    float uu  = fmaf(uix, ujv.x, fmaf(uiy, ujv.y, uiz * ujv.z));

    float pr = (qi * qj) * e1;                         // qq
    pr = fmaf(-s1, fmaf(qj, udi, -(qi * udj)), pr);    // qu
    pr = fmaf(s1, uu, pr);                             // uu iso
    pr = fmaf(-s2, (udi * udj) * rinv2, pr);           // uu aniso

    if (DIAG) pr = self ? 0.0f : pr;
    return pr;
}

__global__ void __launch_bounds__(NT, 4) pair_kernel(
    const float* __restrict__ q, const float* __restrict__ r,
    const float* __restrict__ u, int n, int tiles, float outscale,
    float* __restrict__ out)
{
    // ---- block -> (tile-pair, j-quarter) ----
    int p4 = blockIdx.x;
    int pr = p4 >> 2;
    const int js = p4 & 3;
    int bi = 0;
    while (pr >= tiles - bi) { pr -= tiles - bi; bi++; }
    const int bj = bi + pr;
    const bool diag = (bi == bj);

    __shared__ float4 s_rq[TJ];   // (x, y, z, q)
    __shared__ float4 s_u[TJ];    // (ux, uy, uz, 0)

    const int tx = threadIdx.x;
    const int il = tx & (TI - 1);     // i-lane 0..127
    const int jg = tx >> 7;           // j-group 0..1 (16 j's each)
    const int i  = bi * TI + il;
    const int j0 = bj * TI + js * TJ;

    if (tx < TJ) {
        int j = j0 + tx;
        float4 v;
        if (j < n) { v.x = r[3*j]; v.y = r[3*j+1]; v.z = r[3*j+2]; v.w = q[j]; }
        else       { v.x = 1.0e7f + (float)j; v.y = 0.f; v.z = 0.f; v.w = 0.f; }
        s_rq[tx] = v;
    } else if (tx < 2 * TJ) {
        int jt = tx - TJ, j = j0 + jt;
        float4 v;
        if (j < n) { v.x = u[3*j]; v.y = u[3*j+1]; v.z = u[3*j+2]; v.w = 0.f; }
        else       { v = make_float4(0.f, 0.f, 0.f, 0.f); }
        s_u[jt] = v;
    }

    float qi = 0.f, rix, riy = 0.f, riz = 0.f, uix = 0.f, uiy = 0.f, uiz = 0.f;
    if (i < n) {
        qi  = q[i];
        rix = r[3*i]; riy = r[3*i+1]; riz = r[3*i+2];
        uix = u[3*i]; uiy = u[3*i+1]; uiz = u[3*i+2];
    } else {
        rix = 2.0e7f + (float)i;   // far, q=u=0 -> zero contribution
    }
    __syncthreads();

    double acc = 0.0;
    const int jbeg = jg * (TJ / 2);   // 16 j's per thread

    if (!diag) {
        #pragma unroll
        for (int g = 0; g < TJ / 2; g += 8) {
            float facc = 0.0f;
            #pragma unroll
            for (int k = 0; k < 8; k++) {
                int jj = jbeg + g + k;
                facc += pair_term<false>(rix, riy, riz, qi, uix, uiy, uiz,
                                         s_rq[jj], s_u[jj], false);
            }
            acc += (double)facc;
        }
    } else {
        #pragma unroll
        for (int g = 0; g < TJ / 2; g += 8) {
            float facc = 0.0f;
            #pragma unroll
            for (int k = 0; k < 8; k++) {
                int jj = jbeg + g + k;
                facc += pair_term<true>(rix, riy, riz, qi, uix, uiy, uiz,
                                        s_rq[jj], s_u[jj], (j0 + jj) == i);
            }
            acc += (double)facc;
        }
        acc *= 0.5;   // diagonal tile double-counts each unordered pair
    }

    // ---- deterministic block reduction ----
    #pragma unroll
    for (int off = 16; off > 0; off >>= 1)
        acc += __shfl_down_sync(0xffffffffu, acc, off);

    __shared__ double warp_s[NT / 32];
    if ((tx & 31) == 0) warp_s[tx >> 5] = acc;
    __syncthreads();

    __shared__ bool isLast;
    if (tx == 0) {
        double s = 0.0;
        #pragma unroll
        for (int w = 0; w < NT / 32; w++) s += warp_s[w];
        g_part[blockIdx.x] = s;
        __threadfence();
        unsigned c = atomicAdd(&g_count, 1u);
        isLast = (c == gridDim.x - 1);
    }
    __syncthreads();

    // ---- last block: final reduction (fixed order -> deterministic) ----
    if (isLast) {
        __threadfence();
        const int nB = gridDim.x;
        double s = 0.0;
        for (int k = tx; k < nB; k += NT) s += g_part[k];

        #pragma unroll
        for (int off = 16; off > 0; off >>= 1)
            s += __shfl_down_sync(0xffffffffu, s, off);

        __shared__ double fin_s[NT / 32];
        if ((tx & 31) == 0) fin_s[tx >> 5] = s;
        __syncthreads();
        if (tx == 0) {
            double tot = 0.0;
            #pragma unroll
            for (int w = 0; w < NT / 32; w++) tot += fin_s[w];
            out[0] = (float)(tot * (double)outscale);
            g_count = 0;   // reset for next graph replay
        }
    }
}

extern "C" void kernel_launch(void* const* d_in, const int* in_sizes, int n_in,
                              void* d_out, int out_size)
{
    const float* q = (const float*)d_in[0];
    const float* r = (const float*)d_in[1];
    const float* u = (const float*)d_in[2];
    float* out = (float*)d_out;

    int n = in_sizes[0];
    int tiles = (n + TI - 1) / TI;
    if (tiles > MAX_TILES) tiles = MAX_TILES;

    int nB = tiles * (tiles + 1) * 2;   // 4 j-quarter blocks per triangular tile-pair
    float outscale = (float)(90.0474 / 6.283185307179586476925286766559);

    pair_kernel<<<nB, NT>>>(q, r, u, n, tiles, outscale, out);
}